// round 3
// baseline (speedup 1.0000x reference)
#include <cuda_runtime.h>
#include <math.h>

#define BATCH 8192
#define DIM 64
#define TILE 128
#define NT (BATCH/TILE)          /* 64 row/col tiles   */
#define NTRI (NT*(NT+1)/2)       /* 2080 triangular tiles */
#define SROW 130                 /* padded smem row stride in words (even -> 8B aligned pairs) */
#define SMEM_WORDS (2*DIM*SROW)
#define SMEM_BYTES (SMEM_WORDS*4)

// Scratch (no cudaMalloc allowed): normalized embeddings + reduction accumulators.
__device__ float  g_Xu[BATCH*DIM];
__device__ float  g_Xp[BATCH*DIM];
__device__ double g_acc[3];   // [0] sum of un.pn dots, [1] Su total, [2] Sp total

__device__ __forceinline__ float fast_ex2(float x) {
    float r;
    asm("ex2.approx.ftz.f32 %0, %1;" : "=f"(r) : "f"(x));
    return r;
}

__global__ void zero_acc_kernel() {
    if (threadIdx.x < 3) g_acc[threadIdx.x] = 0.0;
}

// One warp per batch row: gather, normalize, store, and accumulate alignment dot.
__global__ void gather_normalize_kernel(const int* __restrict__ uid,
                                        const int* __restrict__ pid,
                                        const float* __restrict__ utab,
                                        const float* __restrict__ itab) {
    int row  = blockIdx.x * 8 + (threadIdx.x >> 5);
    int lane = threadIdx.x & 31;
    const float* up = utab + (size_t)uid[row] * DIM;
    const float* pp = itab + (size_t)pid[row] * DIM;
    float u0 = up[lane], u1 = up[lane + 32];
    float p0 = pp[lane], p1 = pp[lane + 32];
    float su = u0*u0 + u1*u1;
    float sp = p0*p0 + p1*p1;
#pragma unroll
    for (int o = 16; o; o >>= 1) {
        su += __shfl_xor_sync(0xffffffffu, su, o);
        sp += __shfl_xor_sync(0xffffffffu, sp, o);
    }
    float ru = rsqrtf(su), rp = rsqrtf(sp);
    u0 *= ru; u1 *= ru; p0 *= rp; p1 *= rp;
    g_Xu[row*DIM + lane]      = u0;
    g_Xu[row*DIM + lane + 32] = u1;
    g_Xp[row*DIM + lane]      = p0;
    g_Xp[row*DIM + lane + 32] = p1;
    float d = u0*p0 + u1*p1;
#pragma unroll
    for (int o = 16; o; o >>= 1) d += __shfl_xor_sync(0xffffffffu, d, o);
    if (lane == 0) atomicAdd(&g_acc[0], (double)d);
}

// Triangular-tiled Gram sum: for matrix X (by blockIdx.y), accumulate
// sum over ALL (i,j) of exp(4*<xi,xj> - 4). Off-diagonal tiles weighted x2.
// Inner product uses packed f32x2 FFMA2 (2 FMAs/instr) — ptxas never emits
// this from C++, only via PTX fma.rn.f32x2.
__global__ void __launch_bounds__(256, 2) gram_kernel() {
    extern __shared__ float sm[];
    float* As = sm;                 // [DIM][SROW]  As[k*SROW + i] = X[ti*128+i][k]
    float* Bs = sm + DIM*SROW;

    const float* X = (blockIdx.y == 0) ? g_Xu : g_Xp;
    int b = blockIdx.x;
    // decode triangular tile index (ti <= tj)
    int ti = (int)((2.0*NT + 1.0 - sqrt((2.0*NT+1.0)*(2.0*NT+1.0) - 8.0*(double)b)) * 0.5);
    while (ti*(2*NT - ti + 1)/2 > b) ti--;
    while ((ti+1)*(2*NT - ti)/2 <= b) ti++;
    int tj = ti + (b - ti*(2*NT - ti + 1)/2);

    int tid = threadIdx.x;
    // Load both 128x64 tiles (contiguous 32KB each), transpose into k-major smem.
    const float4* A4 = (const float4*)(X + (size_t)ti*TILE*DIM);
    const float4* B4 = (const float4*)(X + (size_t)tj*TILE*DIM);
#pragma unroll
    for (int i = 0; i < 8; i++) {
        int idx4 = tid + i*256;          // 0..2047 float4s
        float4 av = A4[idx4];
        float4 bv = B4[idx4];
        int w = idx4 * 4;
        int r = w >> 6;                  // row within tile
        int c = w & 63;                  // k
        As[(c+0)*SROW + r] = av.x; As[(c+1)*SROW + r] = av.y;
        As[(c+2)*SROW + r] = av.z; As[(c+3)*SROW + r] = av.w;
        Bs[(c+0)*SROW + r] = bv.x; Bs[(c+1)*SROW + r] = bv.y;
        Bs[(c+2)*SROW + r] = bv.z; Bs[(c+3)*SROW + r] = bv.w;
    }
    __syncthreads();

    int tx = tid & 15;   // column group
    int ty = tid >> 4;   // row group
    // 8 rows (ty + 16u) x 8 cols (pairs {2tx+32v, 2tx+32v+1}) of fp32 accumulators, packed.
    unsigned long long acc[8][4];
#pragma unroll
    for (int u = 0; u < 8; u++)
#pragma unroll
        for (int v = 0; v < 4; v++) acc[u][v] = 0ull;

#pragma unroll 8
    for (int k = 0; k < DIM; k++) {
        const float* Ak = As + k*SROW;
        const unsigned long long* Bk = (const unsigned long long*)(Bs + k*SROW);
        unsigned long long a2[8];
#pragma unroll
        for (int u = 0; u < 8; u++) {
            unsigned int ai = __float_as_uint(Ak[ty + 16*u]);   // broadcast load
            asm("mov.b64 %0, {%1, %1};" : "=l"(a2[u]) : "r"(ai));
        }
        unsigned long long b2[4];
#pragma unroll
        for (int v = 0; v < 4; v++) b2[v] = Bk[tx + 16*v];      // conflict-free LDS.64
#pragma unroll
        for (int u = 0; u < 8; u++)
#pragma unroll
            for (int v = 0; v < 4; v++)
                asm("fma.rn.f32x2 %0, %1, %2, %0;"
                    : "+l"(acc[u][v]) : "l"(a2[u]), "l"(b2[v]));
    }

    // Epilogue: sum exp(4*sim - 4) = exp2(sim*K2 - K2), K2 = 4*log2(e)
    const float K2 = 5.770780163555852f;
    float s = 0.f;
#pragma unroll
    for (int u = 0; u < 8; u++)
#pragma unroll
        for (int v = 0; v < 4; v++) {
            unsigned int lo, hi;
            asm("mov.b64 {%0, %1}, %2;" : "=r"(lo), "=r"(hi) : "l"(acc[u][v]));
            s += fast_ex2(fmaf(__uint_as_float(lo), K2, -K2));
            s += fast_ex2(fmaf(__uint_as_float(hi), K2, -K2));
        }
    if (ti != tj) s *= 2.0f;

    // Block reduce (reuse smem after sync), one double atomic per block.
#pragma unroll
    for (int o = 16; o; o >>= 1) s += __shfl_xor_sync(0xffffffffu, s, o);
    __syncthreads();
    if ((tid & 31) == 0) sm[tid >> 5] = s;
    __syncthreads();
    if (tid < 8) {
        float t = sm[tid];
#pragma unroll
        for (int o = 4; o; o >>= 1) t += __shfl_xor_sync(0xffu, t, o);
        if (tid == 0) atomicAdd(&g_acc[1 + blockIdx.y], (double)t);
    }
}

__global__ void finalize_kernel(float* out) {
    double n = (double)BATCH;
    double align = 2.0 - 2.0 * g_acc[0] / n;
    // pair_mean = ((S_total - n)/2) / (n(n-1)/2) = (S_total - n)/(n(n-1))
    double denom = n * (n - 1.0);
    double uu = log((g_acc[1] - n) / denom);
    double vv = log((g_acc[2] - n) / denom);
    out[0] = (float)(align + 0.5 * (uu + vv));   // GAMMA = 1
}

extern "C" void kernel_launch(void* const* d_in, const int* in_sizes, int n_in,
                              void* d_out, int out_size) {
    (void)in_sizes; (void)n_in; (void)out_size;
    const int*   uid  = (const int*)d_in[0];
    const int*   pid  = (const int*)d_in[1];
    /* d_in[2] = neg_id, unused by the reference loss */
    const float* utab = (const float*)d_in[3];
    const float* itab = (const float*)d_in[4];
    float* out = (float*)d_out;

    cudaFuncSetAttribute(gram_kernel,
                         cudaFuncAttributeMaxDynamicSharedMemorySize, SMEM_BYTES);

    zero_acc_kernel<<<1, 32>>>();
    gather_normalize_kernel<<<BATCH/8, 256>>>(uid, pid, utab, itab);
    dim3 grid(NTRI, 2);
    gram_kernel<<<grid, 256, SMEM_BYTES>>>();
    finalize_kernel<<<1, 1>>>(out);
}

// round 14
// speedup vs baseline: 2.8674x; 2.8674x over previous
#include <cuda_runtime.h>
#include <cuda_bf16.h>
#include <stdint.h>
#include <math.h>

#define BATCH 8192
#define DIM 64
#define TILE 128
#define NT (BATCH/TILE)          /* 64 row/col tiles   */
#define NTRI (NT*(NT+1)/2)       /* 2080 triangular tiles */

// smem: A tile [128 rows x 144B], B tile same, then reduce scratch.
#define SROWB 144                /* 128B data + 16B pad; keeps 16B chunk align, kills LDS conflicts */
#define SM_A   0
#define SM_B   (128*SROWB)
#define SM_RED (2*128*SROWB)
#define SMEM_BYTES (SM_RED + 64)

__device__ __nv_bfloat16 g_Xu[BATCH*DIM];
__device__ __nv_bfloat16 g_Xp[BATCH*DIM];
__device__ double g_acc[3];   // [0] align dots, [1] Su total, [2] Sp total

__device__ __forceinline__ float fast_ex2(float x) {
    float r; asm("ex2.approx.ftz.f32 %0, %1;" : "=f"(r) : "f"(x)); return r;
}

__global__ void zero_acc_kernel() {
    if (threadIdx.x < 3) g_acc[threadIdx.x] = 0.0;
}

// One warp per batch row: gather, fp32 normalize, store bf16, alignment dot fp32.
__global__ void gather_normalize_kernel(const int* __restrict__ uid,
                                        const int* __restrict__ pid,
                                        const float* __restrict__ utab,
                                        const float* __restrict__ itab) {
    int row  = blockIdx.x * 8 + (threadIdx.x >> 5);
    int lane = threadIdx.x & 31;
    const float* up = utab + (size_t)uid[row] * DIM;
    const float* pp = itab + (size_t)pid[row] * DIM;
    float u0 = up[lane], u1 = up[lane + 32];
    float p0 = pp[lane], p1 = pp[lane + 32];
    float su = u0*u0 + u1*u1;
    float sp = p0*p0 + p1*p1;
#pragma unroll
    for (int o = 16; o; o >>= 1) {
        su += __shfl_xor_sync(0xffffffffu, su, o);
        sp += __shfl_xor_sync(0xffffffffu, sp, o);
    }
    float ru = rsqrtf(su), rp = rsqrtf(sp);
    u0 *= ru; u1 *= ru; p0 *= rp; p1 *= rp;
    g_Xu[row*DIM + lane]      = __float2bfloat16(u0);
    g_Xu[row*DIM + lane + 32] = __float2bfloat16(u1);
    g_Xp[row*DIM + lane]      = __float2bfloat16(p0);
    g_Xp[row*DIM + lane + 32] = __float2bfloat16(p1);
    float d = u0*p0 + u1*p1;
#pragma unroll
    for (int o = 16; o; o >>= 1) d += __shfl_xor_sync(0xffffffffu, d, o);
    if (lane == 0) atomicAdd(&g_acc[0], (double)d);
}

// Triangular-tiled Gram sum via mma.sync (HMMA, bf16 x bf16 -> f32).
// Each block: D[128,128] = A[128,64] @ B[128,64]^T, epilogue sums exp(4*sim-4).
// Warp tile 32x64: 2 m-atoms x 8 n-atoms of m16n8k16, K=64 in 4 k-steps.
__global__ void __launch_bounds__(256, 2) gram_mma_kernel() {
    extern __shared__ char smem[];
    int tid = threadIdx.x, wid = tid >> 5, lane = tid & 31;
    int gid = lane >> 2, tig = lane & 3;                 // fragment coords

    const __nv_bfloat16* X = (blockIdx.y == 0) ? g_Xu : g_Xp;
    int b = blockIdx.x;
    int ti = (int)((2.0*NT + 1.0 - sqrt((2.0*NT+1.0)*(2.0*NT+1.0) - 8.0*(double)b)) * 0.5);
    while (ti*(2*NT - ti + 1)/2 > b) ti--;
    while ((ti+1)*(2*NT - ti)/2 <= b) ti++;
    int tj = ti + (b - ti*(2*NT - ti + 1)/2);

    // Load both 128x64 bf16 tiles (16KB each, contiguous) into padded smem.
    // 16B chunk idx: row = idx>>3, chunk = idx&7 -> dst row*144 + chunk*16.
    const uint4* A4 = (const uint4*)(X + (size_t)ti*TILE*DIM);
    const uint4* B4 = (const uint4*)(X + (size_t)tj*TILE*DIM);
#pragma unroll
    for (int i = 0; i < 4; i++) {
        int idx = tid + i*256;            // 0..1023
        int dst = (idx >> 3)*SROWB + (idx & 7)*16;
        *(uint4*)(smem + SM_A + dst) = A4[idx];
        *(uint4*)(smem + SM_B + dst) = B4[idx];
    }
    __syncthreads();

    int warpRow = (wid & 3) * 32;         // 4 warps over 128 rows
    int warpCol = (wid >> 2) * 64;        // 2 warps over 128 cols

    float d[2][8][4];
#pragma unroll
    for (int am = 0; am < 2; am++)
#pragma unroll
        for (int na = 0; na < 8; na++)
#pragma unroll
            for (int e = 0; e < 4; e++) d[am][na][e] = 0.f;

#pragma unroll
    for (int ks = 0; ks < 4; ks++) {
        int kb = ks*32 + tig*4;           // byte offset of this thread's k pair
        unsigned int a_[2][4];
#pragma unroll
        for (int am = 0; am < 2; am++) {
            const char* base = smem + SM_A + (warpRow + am*16 + gid)*SROWB + kb;
            a_[am][0] = *(const unsigned int*)(base);
            a_[am][1] = *(const unsigned int*)(base + 8*SROWB);
            a_[am][2] = *(const unsigned int*)(base + 16);
            a_[am][3] = *(const unsigned int*)(base + 8*SROWB + 16);
        }
        unsigned int b_[8][2];
#pragma unroll
        for (int na = 0; na < 8; na++) {
            const char* base = smem + SM_B + (warpCol + na*8 + gid)*SROWB + kb;
            b_[na][0] = *(const unsigned int*)(base);
            b_[na][1] = *(const unsigned int*)(base + 16);
        }
#pragma unroll
        for (int am = 0; am < 2; am++)
#pragma unroll
            for (int na = 0; na < 8; na++)
                asm("mma.sync.aligned.m16n8k16.row.col.f32.bf16.bf16.f32 "
                    "{%0,%1,%2,%3}, {%4,%5,%6,%7}, {%8,%9}, {%0,%1,%2,%3};"
                    : "+f"(d[am][na][0]), "+f"(d[am][na][1]),
                      "+f"(d[am][na][2]), "+f"(d[am][na][3])
                    : "r"(a_[am][0]), "r"(a_[am][1]), "r"(a_[am][2]), "r"(a_[am][3]),
                      "r"(b_[na][0]), "r"(b_[na][1]));
    }

    // Epilogue: sum exp(4*sim-4) = exp2(sim*K2 - K2).
    const float K2 = 5.770780163555852f;   // 4*log2(e)
    float s0 = 0.f, s1 = 0.f, s2 = 0.f, s3 = 0.f;
#pragma unroll
    for (int am = 0; am < 2; am++)
#pragma unroll
        for (int na = 0; na < 8; na++) {
            s0 += fast_ex2(fmaf(d[am][na][0], K2, -K2));
            s1 += fast_ex2(fmaf(d[am][na][1], K2, -K2));
            s2 += fast_ex2(fmaf(d[am][na][2], K2, -K2));
            s3 += fast_ex2(fmaf(d[am][na][3], K2, -K2));
        }
    float s = (s0 + s1) + (s2 + s3);
    if (ti != tj) s *= 2.0f;

#pragma unroll
    for (int o = 16; o; o >>= 1) s += __shfl_xor_sync(0xffffffffu, s, o);
    if (lane == 0) *(volatile float*)(smem + SM_RED + (wid<<2)) = s;
    __syncthreads();
    if (tid == 0) {
        volatile float* red = (volatile float*)(smem + SM_RED);
        float t = ((red[0] + red[1]) + (red[2] + red[3]))
                + ((red[4] + red[5]) + (red[6] + red[7]));
        atomicAdd(&g_acc[1 + blockIdx.y], (double)t);
    }
}

__global__ void finalize_kernel(float* out) {
    double n = (double)BATCH;
    double align = 2.0 - 2.0 * g_acc[0] / n;
    double denom = n * (n - 1.0);
    double uu = log((g_acc[1] - n) / denom);
    double vv = log((g_acc[2] - n) / denom);
    out[0] = (float)(align + 0.5 * (uu + vv));   // GAMMA = 1
}

extern "C" void kernel_launch(void* const* d_in, const int* in_sizes, int n_in,
                              void* d_out, int out_size) {
    (void)in_sizes; (void)n_in; (void)out_size;
    const int*   uid  = (const int*)d_in[0];
    const int*   pid  = (const int*)d_in[1];
    /* d_in[2] = neg_id, unused by the reference loss */
    const float* utab = (const float*)d_in[3];
    const float* itab = (const float*)d_in[4];
    float* out = (float*)d_out;

    cudaFuncSetAttribute(gram_mma_kernel,
                         cudaFuncAttributeMaxDynamicSharedMemorySize, SMEM_BYTES);

    zero_acc_kernel<<<1, 32>>>();
    gather_normalize_kernel<<<BATCH/8, 256>>>(uid, pid, utab, itab);
    dim3 grid(NTRI, 2);
    gram_mma_kernel<<<grid, 256, SMEM_BYTES>>>();
    finalize_kernel<<<1, 1>>>(out);
}